// round 1
// baseline (speedup 1.0000x reference)
#include <cuda_runtime.h>
#include <math.h>

// Problem constants
#define BATCH 32
#define TT 4096
#define DD 512
#define MM (BATCH * TT)   // 131072 rows

// Scratch (device globals; no allocation allowed)
__device__ float g_e_t[MM];          // attention logits e_t[b*T + t]
__device__ float g_dec[BATCH * DD];  // dec_features[b*D + e]

// ---------------------------------------------------------------------------
// Zero scratch + context output region (d_out is poisoned each run)
// ---------------------------------------------------------------------------
__global__ __launch_bounds__(256) void zero_kernel(float* __restrict__ ctx) {
    int i = blockIdx.x * 256 + threadIdx.x;
    if (i < MM) g_e_t[i] = 0.0f;
    if (i < BATCH * DD) ctx[i] = 0.0f;
}

// ---------------------------------------------------------------------------
// dec_features[b][e] = sum_d s_t[b][d] * W_s[d][e] + b_s[e]
// 16384 outputs, one thread each; W_s rows read coalesced across e.
// ---------------------------------------------------------------------------
__global__ __launch_bounds__(256) void dec_kernel(
    const float* __restrict__ s, const float* __restrict__ Ws,
    const float* __restrict__ bs)
{
    int idx = blockIdx.x * 256 + threadIdx.x;   // 0..16383
    int b = idx >> 9;
    int e = idx & 511;
    float acc = bs[e];
    const float* sp = s + b * DD;
#pragma unroll 8
    for (int d = 0; d < DD; d++)
        acc += sp[d] * Ws[d * DD + e];
    g_dec[idx] = acc;
}

// ---------------------------------------------------------------------------
// Fused score GEMM:
//   feat[row][n] = sum_k h[row][k]*Wh[k][n] + dec[b][n] + cov[row]*Wc[n]
//   e_t[row]    += sum_{n in this block's N-chunk} V[n] * tanh(feat[row][n])
// Tiling: BM=128, BN=128, BK=8; 256 threads; 8x8 microtile per thread.
// grid = (M/128 = 1024, N/128 = 4). T divides BM evenly so each M-tile has
// a single batch index b = row0 >> 12, and cov index == row directly.
// ---------------------------------------------------------------------------
__global__ __launch_bounds__(256) void fused_score_gemm(
    const float* __restrict__ h, const float* __restrict__ Wh,
    const float* __restrict__ cov, const float* __restrict__ Wc,
    const float* __restrict__ V)
{
    __shared__ float As[8][128];   // transposed A tile: As[k][row]
    __shared__ float Bs[8][128];   // Bs[k][col]

    const int row0 = blockIdx.x * 128;
    const int col0 = blockIdx.y * 128;
    const int b    = row0 >> 12;          // row0 / 4096
    const int tid  = threadIdx.x;
    const int ty   = tid >> 4;            // 0..15 -> rows ty*8..
    const int tx   = tid & 15;            // 0..15 -> cols tx*8..

    // Global-load mapping
    const int arow  = tid >> 1;           // 0..127
    const int acol4 = (tid & 1) * 4;      // 0 or 4
    const int brow  = tid >> 5;           // 0..7
    const int bcol4 = (tid & 31) * 4;     // 0..124

    const float* Aptr = h + (long)(row0 + arow) * DD + acol4;
    const float* Bptr = Wh + (long)brow * DD + col0 + bcol4;

    float acc[8][8];
#pragma unroll
    for (int i = 0; i < 8; i++)
#pragma unroll
        for (int j = 0; j < 8; j++) acc[i][j] = 0.0f;

    for (int kt = 0; kt < DD; kt += 8) {
        float4 av = *(const float4*)(Aptr + kt);
        float4 bv = *(const float4*)(Bptr + (long)kt * DD);
        As[acol4 + 0][arow] = av.x;
        As[acol4 + 1][arow] = av.y;
        As[acol4 + 2][arow] = av.z;
        As[acol4 + 3][arow] = av.w;
        *(float4*)&Bs[brow][bcol4] = bv;
        __syncthreads();

#pragma unroll
        for (int k = 0; k < 8; k++) {
            float4 a0 = *(const float4*)&As[k][ty * 8];
            float4 a1 = *(const float4*)&As[k][ty * 8 + 4];
            float4 b0 = *(const float4*)&Bs[k][tx * 8];
            float4 b1 = *(const float4*)&Bs[k][tx * 8 + 4];
            float ar[8] = {a0.x, a0.y, a0.z, a0.w, a1.x, a1.y, a1.z, a1.w};
            float br[8] = {b0.x, b0.y, b0.z, b0.w, b1.x, b1.y, b1.z, b1.w};
#pragma unroll
            for (int i = 0; i < 8; i++)
#pragma unroll
                for (int j = 0; j < 8; j++)
                    acc[i][j] += ar[i] * br[j];
        }
        __syncthreads();
    }

    // Epilogue: add dec/coverage terms, tanh, dot with V, reduce over cols.
    float dv[8], wcv[8], vv[8];
#pragma unroll
    for (int j = 0; j < 8; j++) {
        int n = col0 + tx * 8 + j;
        dv[j]  = g_dec[b * DD + n];
        wcv[j] = Wc[n];
        vv[j]  = V[n];
    }

#pragma unroll
    for (int i = 0; i < 8; i++) {
        int row = row0 + ty * 8 + i;          // == b*T + t
        float cv = cov[row];
        float s = 0.0f;
#pragma unroll
        for (int j = 0; j < 8; j++) {
            float f = acc[i][j] + dv[j] + cv * wcv[j];
            s += vv[j] * tanhf(f);
        }
        // reduce across the 16 tx lanes (segments of width 16 inside warp)
#pragma unroll
        for (int off = 8; off > 0; off >>= 1)
            s += __shfl_down_sync(0xffffffffu, s, off, 16);
        if (tx == 0) atomicAdd(&g_e_t[row], s);
    }
}

// ---------------------------------------------------------------------------
// Softmax over T per batch row; also emits new_coverage = coverage + a_t
// ---------------------------------------------------------------------------
__global__ __launch_bounds__(256) void softmax_kernel(
    const float* __restrict__ cov, float* __restrict__ a_out,
    float* __restrict__ ncov_out)
{
    int b = blockIdx.x;
    int tid = threadIdx.x;
    const float* e = g_e_t + b * TT;
    __shared__ float red[256];

    float ev[16];
    float m = -1e30f;
#pragma unroll
    for (int k = 0; k < 16; k++) {
        ev[k] = e[tid + k * 256];
        m = fmaxf(m, ev[k]);
    }
    red[tid] = m; __syncthreads();
    for (int s = 128; s > 0; s >>= 1) {
        if (tid < s) red[tid] = fmaxf(red[tid], red[tid + s]);
        __syncthreads();
    }
    float M = red[0]; __syncthreads();

    float sum = 0.0f;
#pragma unroll
    for (int k = 0; k < 16; k++) {
        ev[k] = expf(ev[k] - M);
        sum += ev[k];
    }
    red[tid] = sum; __syncthreads();
    for (int s = 128; s > 0; s >>= 1) {
        if (tid < s) red[tid] += red[tid + s];
        __syncthreads();
    }
    float inv = 1.0f / red[0];

#pragma unroll
    for (int k = 0; k < 16; k++) {
        int i = b * TT + tid + k * 256;
        float a = ev[k] * inv;
        a_out[i] = a;
        ncov_out[i] = cov[i] + a;
    }
}

// ---------------------------------------------------------------------------
// context[b][d] = sum_t a[b][t] * h[b][t][d]
// Split T into 32 chunks of 128; grid = (B*32), block = 512 (one thread per d).
// Partial sums combined with atomicAdd (ctx pre-zeroed).
// ---------------------------------------------------------------------------
__global__ __launch_bounds__(512) void context_kernel(
    const float* __restrict__ h, const float* __restrict__ a,
    float* __restrict__ ctx)
{
    int b  = blockIdx.x >> 5;
    int tc = blockIdx.x & 31;
    int d  = threadIdx.x;
    int t0 = tc * 128;
    const float* hp = h + ((long)b * TT + t0) * DD + d;
    const float* ap = a + b * TT + t0;
    float acc = 0.0f;
#pragma unroll 4
    for (int t = 0; t < 128; t++)
        acc += ap[t] * hp[(long)t * DD];
    atomicAdd(&ctx[b * DD + d], acc);
}

// ---------------------------------------------------------------------------
extern "C" void kernel_launch(void* const* d_in, const int* in_sizes, int n_in,
                              void* d_out, int out_size)
{
    const float* h   = (const float*)d_in[0];  // (B,T,D)
    const float* s   = (const float*)d_in[1];  // (B,D)
    const float* cov = (const float*)d_in[2];  // (B,T)
    const float* Wh  = (const float*)d_in[3];  // (D,D)
    const float* Ws  = (const float*)d_in[4];  // (D,D)
    const float* bs  = (const float*)d_in[5];  // (D,)
    const float* Wc  = (const float*)d_in[6];  // (1,D)
    const float* V   = (const float*)d_in[7];  // (D,1)

    float* out   = (float*)d_out;
    float* ctx   = out;                        // (B,D)    = 16384
    float* a_out = out + BATCH * DD;           // (B,T)    = 131072
    float* ncov  = a_out + MM;                 // (B,T)    = 131072

    zero_kernel<<<512, 256>>>(ctx);
    dec_kernel<<<64, 256>>>(s, Ws, bs);
    fused_score_gemm<<<dim3(MM / 128, DD / 128), 256>>>(h, Wh, cov, Wc, V);
    softmax_kernel<<<BATCH, 256>>>(cov, a_out, ncov);
    context_kernel<<<BATCH * 32, 512>>>(h, a_out, ctx);
}

// round 4
// speedup vs baseline: 2.8649x; 2.8649x over previous
#include <cuda_runtime.h>
#include <math.h>
#include <stdint.h>

#define BATCH 32
#define TT 4096
#define DD 512
#define MM (BATCH * TT)

#define BM 128
#define BN 128
#define BKK 16
#define AST 20    // A smem row stride (floats), conflict-free for a-frag loads
#define BST 136   // B smem row stride (floats), conflict-free for b-frag loads

// ---------------- device scratch (no allocation allowed) -------------------
__device__ float g_e_t[MM];
__device__ float g_dec[BATCH * DD];

// ---------------- PTX helpers ----------------------------------------------
__device__ __forceinline__ uint32_t smem_u32(const void* p) {
    uint32_t a;
    asm("{ .reg .u64 t; cvta.to.shared.u64 t, %1; cvt.u32.u64 %0, t; }" : "=r"(a) : "l"(p));
    return a;
}
__device__ __forceinline__ void cp16(uint32_t dst, const void* src) {
    asm volatile("cp.async.cg.shared.global [%0], [%1], 16;" :: "r"(dst), "l"(src));
}
__device__ __forceinline__ void cp_commit() {
    asm volatile("cp.async.commit_group;" ::: "memory");
}
__device__ __forceinline__ void cp_wait1() {
    asm volatile("cp.async.wait_group 1;" ::: "memory");
}
__device__ __forceinline__ void cp_wait0() {
    asm volatile("cp.async.wait_group 0;" ::: "memory");
}
__device__ __forceinline__ float tanhap(float x) {
    float y; asm("tanh.approx.f32 %0, %1;" : "=f"(y) : "f"(x)); return y;
}
__device__ __forceinline__ void mma_tf32(float* c, const uint32_t* a, const uint32_t* b) {
    asm volatile(
        "mma.sync.aligned.m16n8k8.row.col.f32.tf32.tf32.f32 "
        "{%0,%1,%2,%3}, {%4,%5,%6,%7}, {%8,%9}, {%0,%1,%2,%3};"
        : "+f"(c[0]), "+f"(c[1]), "+f"(c[2]), "+f"(c[3])
        : "r"(a[0]), "r"(a[1]), "r"(a[2]), "r"(a[3]), "r"(b[0]), "r"(b[1]));
}

// ---------------------------------------------------------------------------
__global__ __launch_bounds__(256) void zero_kernel(float* __restrict__ ctx) {
    int i = blockIdx.x * 256 + threadIdx.x;
    if (i < MM) g_e_t[i] = 0.0f;
    if (i < BATCH * DD) ctx[i] = 0.0f;
}

__global__ __launch_bounds__(256) void dec_kernel(
    const float* __restrict__ s, const float* __restrict__ Ws, const float* __restrict__ bs)
{
    int idx = blockIdx.x * 256 + threadIdx.x;
    int b = idx >> 9, e = idx & 511;
    float acc = bs[e];
    const float* sp = s + b * DD;
#pragma unroll 8
    for (int d = 0; d < DD; d++) acc += sp[d] * Ws[d * DD + e];
    g_dec[idx] = acc;
}

// ---------------------------------------------------------------------------
// Fused score GEMM on tensor cores (mma.sync tf32) + tanh/V-dot epilogue.
//   feat = h @ Wh + dec[b] + cov*Wc ;  e_t[row] += sum_n V[n]*tanh(feat[row][n])
// Block: 128x128 tile, BK=16, 256 threads, 8 warps (2 M x 4 N), 64x32/warp.
// ---------------------------------------------------------------------------
__global__ __launch_bounds__(256) void fused_score_gemm(
    const float* __restrict__ h, const float* __restrict__ Wh,
    const float* __restrict__ cov, const float* __restrict__ Wc,
    const float* __restrict__ V)
{
    __shared__ alignas(16) float As[2][BM * AST];
    __shared__ alignas(16) float Bs[2][BKK * BST];
    __shared__ float sV[BN], sWc[BN], sDec[BN];

    const int tid = threadIdx.x;
    const int lane = tid & 31, wid = tid >> 5;
    const int wm = wid >> 2, wn = wid & 3;          // warp grid 2 x 4
    const int lr = lane >> 2, lc = lane & 3;
    const int row0 = blockIdx.x * BM;
    const int col0 = blockIdx.y * BN;
    const int b = row0 >> 12;

    if (tid < BN) {
        sV[tid] = V[col0 + tid];
        sWc[tid] = Wc[col0 + tid];
        sDec[tid] = g_dec[b * DD + col0 + tid];
    }

    // ---- global -> smem tile loader (cp.async), 4 x 16B per thread --------
    auto load_tiles = [&](int stage, int kt) {
#pragma unroll
        for (int i = 0; i < 2; i++) {
            int cid = tid + i * 256;                 // 0..511
            int m = cid >> 2, c = cid & 3;
            cp16(smem_u32(&As[stage][m * AST + c * 4]),
                 h + (size_t)(row0 + m) * DD + kt * BKK + c * 4);
        }
#pragma unroll
        for (int i = 0; i < 2; i++) {
            int cid = tid + i * 256;
            int k = cid >> 5, n4 = cid & 31;
            cp16(smem_u32(&Bs[stage][k * BST + n4 * 4]),
                 Wh + (size_t)(kt * BKK + k) * DD + col0 + n4 * 4);
        }
        cp_commit();
    };

    float acc[4][4][4];
#pragma unroll
    for (int mf = 0; mf < 4; mf++)
#pragma unroll
        for (int nf = 0; nf < 4; nf++)
#pragma unroll
            for (int c = 0; c < 4; c++) acc[mf][nf][c] = 0.0f;

    load_tiles(0, 0);

    const int NKT = DD / BKK;                        // 32
    for (int kt = 0; kt < NKT; kt++) {
        if (kt + 1 < NKT) { load_tiles((kt + 1) & 1, kt + 1); cp_wait1(); }
        else              { cp_wait0(); }
        __syncthreads();

        const float* A = As[kt & 1];
        const float* B = Bs[kt & 1];
#pragma unroll
        for (int k8 = 0; k8 < BKK; k8 += 8) {
            uint32_t a[4][4], bb[4][2];
#pragma unroll
            for (int mf = 0; mf < 4; mf++) {
                int m0 = wm * 64 + mf * 16 + lr;
                a[mf][0] = __float_as_uint(A[m0 * AST + k8 + lc]);
                a[mf][1] = __float_as_uint(A[(m0 + 8) * AST + k8 + lc]);
                a[mf][2] = __float_as_uint(A[m0 * AST + k8 + lc + 4]);
                a[mf][3] = __float_as_uint(A[(m0 + 8) * AST + k8 + lc + 4]);
            }
#pragma unroll
            for (int nf = 0; nf < 4; nf++) {
                int n0 = wn * 32 + nf * 8 + lr;
                bb[nf][0] = __float_as_uint(B[(k8 + lc) * BST + n0]);
                bb[nf][1] = __float_as_uint(B[(k8 + lc + 4) * BST + n0]);
            }
#pragma unroll
            for (int mf = 0; mf < 4; mf++)
#pragma unroll
                for (int nf = 0; nf < 4; nf++)
                    mma_tf32(acc[mf][nf], a[mf], bb[nf]);
        }
        __syncthreads();
    }

    // ---- epilogue: partial e_t over this block's 128 cols -----------------
#pragma unroll
    for (int mf = 0; mf < 4; mf++) {
#pragma unroll
        for (int h2 = 0; h2 < 2; h2++) {
            int row = row0 + wm * 64 + mf * 16 + lr + h2 * 8;
            float cv = cov[row];
            float s = 0.0f;
#pragma unroll
            for (int nf = 0; nf < 4; nf++) {
#pragma unroll
                for (int c2 = 0; c2 < 2; c2++) {
                    int nl = wn * 32 + nf * 8 + 2 * lc + c2;
                    float f = acc[mf][nf][h2 * 2 + c2] + sDec[nl] + cv * sWc[nl];
                    s += sV[nl] * tanhap(f);
                }
            }
            s += __shfl_xor_sync(0xffffffffu, s, 1, 4);
            s += __shfl_xor_sync(0xffffffffu, s, 2, 4);
            if (lc == 0) atomicAdd(&g_e_t[row], s);
        }
    }
}

// ---------------------------------------------------------------------------
__global__ __launch_bounds__(256) void softmax_kernel(
    const float* __restrict__ cov, float* __restrict__ a_out, float* __restrict__ ncov_out)
{
    int b = blockIdx.x;
    int tid = threadIdx.x;
    const float* e = g_e_t + b * TT;
    __shared__ float red[256];
    float ev[16];
    float m = -1e30f;
#pragma unroll
    for (int k = 0; k < 16; k++) { ev[k] = e[tid + k * 256]; m = fmaxf(m, ev[k]); }
    red[tid] = m; __syncthreads();
    for (int s = 128; s > 0; s >>= 1) {
        if (tid < s) red[tid] = fmaxf(red[tid], red[tid + s]);
        __syncthreads();
    }
    float M = red[0]; __syncthreads();
    float sum = 0.0f;
#pragma unroll
    for (int k = 0; k < 16; k++) { ev[k] = expf(ev[k] - M); sum += ev[k]; }
    red[tid] = sum; __syncthreads();
    for (int s = 128; s > 0; s >>= 1) {
        if (tid < s) red[tid] += red[tid + s];
        __syncthreads();
    }
    float inv = 1.0f / red[0];
#pragma unroll
    for (int k = 0; k < 16; k++) {
        int i = b * TT + tid + k * 256;
        float a = ev[k] * inv;
        a_out[i] = a;
        ncov_out[i] = cov[i] + a;
    }
}

__global__ __launch_bounds__(512) void context_kernel(
    const float* __restrict__ h, const float* __restrict__ a, float* __restrict__ ctx)
{
    int b = blockIdx.x >> 5;
    int tc = blockIdx.x & 31;
    int d = threadIdx.x;
    int t0 = tc * 128;
    const float* hp = h + ((size_t)b * TT + t0) * DD + d;
    const float* ap = a + b * TT + t0;
    float acc = 0.0f;
#pragma unroll 4
    for (int t = 0; t < 128; t++) acc += ap[t] * hp[(size_t)t * DD];
    atomicAdd(&ctx[b * DD + d], acc);
}

// ---------------------------------------------------------------------------
extern "C" void kernel_launch(void* const* d_in, const int* in_sizes, int n_in,
                              void* d_out, int out_size)
{
    const float* h   = (const float*)d_in[0];
    const float* s   = (const float*)d_in[1];
    const float* cov = (const float*)d_in[2];
    const float* Wh  = (const float*)d_in[3];
    const float* Ws  = (const float*)d_in[4];
    const float* bs  = (const float*)d_in[5];
    const float* Wc  = (const float*)d_in[6];
    const float* V   = (const float*)d_in[7];

    float* out   = (float*)d_out;
    float* ctx   = out;
    float* a_out = out + BATCH * DD;
    float* ncov  = a_out + MM;

    zero_kernel<<<512, 256>>>(ctx);
    dec_kernel<<<64, 256>>>(s, Ws, bs);
    fused_score_gemm<<<dim3(MM / BM, DD / BN), 256>>>(h, Wh, cov, Wc, V);
    softmax_kernel<<<BATCH, 256>>>(cov, a_out, ncov);
    context_kernel<<<BATCH * 32, 512>>>(h, a_out, ctx);
}

// round 5
// speedup vs baseline: 5.1533x; 1.7988x over previous
#include <cuda_runtime.h>
#include <cuda_fp16.h>
#include <math.h>
#include <stdint.h>

#define BATCH 32
#define TT 4096
#define DD 512
#define MM (BATCH * TT)

#define LDA 520          // A16 smem row stride in halves (128 rows x 512 K)
#define LDB 136          // B16 smem row stride in halves (32 k-rows x 128 n)

// ---------------- device scratch (no allocation allowed) -------------------
__device__ float g_e_t[MM];
__device__ float g_dec[BATCH * DD];
__device__ __half g_Wh16[DD * DD];   // fp16 copy of W_h [k][n]

// ---------------- smem layout (bytes) --------------------------------------
#define SM_A     0                       // 128 * LDA * 2 = 133120
#define SM_B0    133120                  // 32 * LDB * 2 = 8704
#define SM_B1    (SM_B0 + 8704)
#define SM_V     (SM_B1 + 8704)          // float[512]
#define SM_WC    (SM_V + 2048)
#define SM_DEC   (SM_WC + 2048)
#define SM_ESM   (SM_DEC + 2048)         // float[128]
#define SM_TOTAL (SM_ESM + 512 + 512)    // 157696

// ---------------- PTX helpers ----------------------------------------------
__device__ __forceinline__ uint32_t smem_u32(const void* p) {
    uint32_t a;
    asm("{ .reg .u64 t; cvta.to.shared.u64 t, %1; cvt.u32.u64 %0, t; }" : "=r"(a) : "l"(p));
    return a;
}
__device__ __forceinline__ void cp16(uint32_t dst, const void* src) {
    asm volatile("cp.async.cg.shared.global [%0], [%1], 16;" :: "r"(dst), "l"(src));
}
__device__ __forceinline__ void cp_commit() {
    asm volatile("cp.async.commit_group;" ::: "memory");
}
__device__ __forceinline__ void cp_wait1() {
    asm volatile("cp.async.wait_group 1;" ::: "memory");
}
__device__ __forceinline__ void cp_wait0() {
    asm volatile("cp.async.wait_group 0;" ::: "memory");
}
__device__ __forceinline__ float tanhap(float x) {
    float y; asm("tanh.approx.f32 %0, %1;" : "=f"(y) : "f"(x)); return y;
}
__device__ __forceinline__ void ldsm_x4(uint32_t* r, uint32_t addr) {
    asm volatile("ldmatrix.sync.aligned.m8n8.x4.shared.b16 {%0,%1,%2,%3}, [%4];"
                 : "=r"(r[0]), "=r"(r[1]), "=r"(r[2]), "=r"(r[3]) : "r"(addr));
}
__device__ __forceinline__ void ldsm_x4_t(uint32_t* r, uint32_t addr) {
    asm volatile("ldmatrix.sync.aligned.m8n8.x4.trans.shared.b16 {%0,%1,%2,%3}, [%4];"
                 : "=r"(r[0]), "=r"(r[1]), "=r"(r[2]), "=r"(r[3]) : "r"(addr));
}
__device__ __forceinline__ void mma_f16(float* c, const uint32_t* a, const uint32_t* b) {
    asm volatile(
        "mma.sync.aligned.m16n8k16.row.col.f32.f16.f16.f32 "
        "{%0,%1,%2,%3}, {%4,%5,%6,%7}, {%8,%9}, {%0,%1,%2,%3};"
        : "+f"(c[0]), "+f"(c[1]), "+f"(c[2]), "+f"(c[3])
        : "r"(a[0]), "r"(a[1]), "r"(a[2]), "r"(a[3]), "r"(b[0]), "r"(b[1]));
}

// ---------------------------------------------------------------------------
__global__ __launch_bounds__(256) void zero_kernel(float* __restrict__ ctx) {
    int i = blockIdx.x * 256 + threadIdx.x;
    if (i < BATCH * DD) ctx[i] = 0.0f;
}

__global__ __launch_bounds__(256) void prep_wh_kernel(const float* __restrict__ Wh) {
    int i = blockIdx.x * 256 + threadIdx.x;   // 0..262143
    g_Wh16[i] = __float2half(Wh[i]);
}

__global__ __launch_bounds__(256) void dec_kernel(
    const float* __restrict__ s, const float* __restrict__ Ws, const float* __restrict__ bs)
{
    int idx = blockIdx.x * 256 + threadIdx.x;
    int b = idx >> 9, e = idx & 511;
    float acc = bs[e];
    const float* sp = s + b * DD;
#pragma unroll 8
    for (int d = 0; d < DD; d++) acc += sp[d] * Ws[d * DD + e];
    g_dec[idx] = acc;
}

// ---------------------------------------------------------------------------
// fp16 tensor-core score GEMM, fused tanh/V-dot epilogue.
// CTA: 128 rows x full N=512 (4 N-blocks of 128), K resident in smem as fp16.
// 256 threads, 8 warps (2 M x 4 N), 64x32 per warp, BK=32 double-buffered B.
// ---------------------------------------------------------------------------
__global__ __launch_bounds__(256) void fused_score_gemm(
    const float* __restrict__ h, const float* __restrict__ cov,
    const float* __restrict__ Wc, const float* __restrict__ V)
{
    extern __shared__ char smem[];
    __half* A16 = (__half*)(smem + SM_A);
    float* sV   = (float*)(smem + SM_V);
    float* sWc  = (float*)(smem + SM_WC);
    float* sDec = (float*)(smem + SM_DEC);
    float* eSm  = (float*)(smem + SM_ESM);

    const int tid = threadIdx.x;
    const int lane = tid & 31, wid = tid >> 5;
    const int wm = wid >> 2, wn = wid & 3;           // 2 x 4 warp grid
    const int lr = lane >> 2, lc = lane & 3;
    const int row0 = blockIdx.x * 128;
    const int b = row0 >> 12;

    // epilogue constants + e accumulator init
    for (int i = tid; i < DD; i += 256) {
        sV[i] = V[i]; sWc[i] = Wc[i]; sDec[i] = g_dec[b * DD + i];
    }
    if (tid < 128) eSm[tid] = 0.0f;

    // ---- load h rows (fp32) -> convert -> resident fp16 A slab ------------
    {
        const float2* hp = (const float2*)(h + (size_t)row0 * DD);
#pragma unroll
        for (int i = 0; i < 128; i++) {
            int idx2 = tid + i * 256;                // 0..32767
            int m = idx2 >> 8, c2 = idx2 & 255;      // k = 2*c2
            float2 v = hp[(size_t)m * 256 + c2];
            *(__half2*)&A16[m * LDA + 2 * c2] = __floats2half2_rn(v.x, v.y);
        }
    }
    __syncthreads();

    const uint32_t sbB[2] = {smem_u32(smem + SM_B0), smem_u32(smem + SM_B1)};
    const uint32_t sbA = smem_u32(A16);

    // per-row coverage values (rows this thread's accs touch)
    float cvr[4][2];
#pragma unroll
    for (int mf = 0; mf < 4; mf++)
#pragma unroll
        for (int h2 = 0; h2 < 2; h2++)
            cvr[mf][h2] = cov[row0 + wm * 64 + mf * 16 + lr + h2 * 8];

    float acc_e[4][2];
#pragma unroll
    for (int mf = 0; mf < 4; mf++) { acc_e[mf][0] = 0.0f; acc_e[mf][1] = 0.0f; }

    // B tile loader: 32 k-rows x 128 n halves (8KB), 2 chunks of 16B/thread
    auto load_b = [&](int stage, int nb, int kt) {
#pragma unroll
        for (int i = 0; i < 2; i++) {
            int cid = tid + i * 256;                 // 0..511
            int k = cid >> 4, n8 = cid & 15;
            cp16(sbB[stage] + (k * LDB + n8 * 8) * 2,
                 g_Wh16 + (size_t)(kt * 32 + k) * DD + nb * 128 + n8 * 8);
        }
        cp_commit();
    };

    for (int nb = 0; nb < 4; nb++) {
        float acc[4][4][4];
#pragma unroll
        for (int mf = 0; mf < 4; mf++)
#pragma unroll
            for (int nf = 0; nf < 4; nf++)
#pragma unroll
                for (int c = 0; c < 4; c++) acc[mf][nf][c] = 0.0f;

        load_b(0, nb, 0);

        for (int kt = 0; kt < 16; kt++) {
            if (kt + 1 < 16) { load_b((kt + 1) & 1, nb, kt + 1); cp_wait1(); }
            else             { cp_wait0(); }
            __syncthreads();

            const uint32_t B = sbB[kt & 1];
#pragma unroll
            for (int ks = 0; ks < 2; ks++) {
                const int k0 = kt * 32 + ks * 16;    // global k for A
                uint32_t a[4][4], bb[2][4];
#pragma unroll
                for (int mf = 0; mf < 4; mf++) {
                    int row = wm * 64 + mf * 16 + (lane & 15);
                    int col = k0 + ((lane >> 4) << 3);
                    ldsm_x4(a[mf], sbA + (row * LDA + col) * 2);
                }
#pragma unroll
                for (int p = 0; p < 2; p++) {
                    int krow = ks * 16 + (lane & 15);
                    int ncol = wn * 32 + p * 16 + ((lane >> 4) << 3);
                    ldsm_x4_t(bb[p], B + (krow * LDB + ncol) * 2);
                }
#pragma unroll
                for (int mf = 0; mf < 4; mf++) {
                    mma_f16(acc[mf][0], a[mf], &bb[0][0]);
                    mma_f16(acc[mf][1], a[mf], &bb[0][2]);
                    mma_f16(acc[mf][2], a[mf], &bb[1][0]);
                    mma_f16(acc[mf][3], a[mf], &bb[1][2]);
                }
            }
            __syncthreads();
        }

        // epilogue for this N-block: accumulate V . tanh(feat)
#pragma unroll
        for (int mf = 0; mf < 4; mf++) {
#pragma unroll
            for (int h2 = 0; h2 < 2; h2++) {
                float cv = cvr[mf][h2];
                float s = 0.0f;
#pragma unroll
                for (int nf = 0; nf < 4; nf++) {
#pragma unroll
                    for (int c2 = 0; c2 < 2; c2++) {
                        int nl = nb * 128 + wn * 32 + nf * 8 + 2 * lc + c2;
                        float f = acc[mf][nf][h2 * 2 + c2] + sDec[nl] + cv * sWc[nl];
                        s += sV[nl] * tanhap(f);
                    }
                }
                acc_e[mf][h2] += s;
            }
        }
    }

    // reduce across lc quad + wn warps via smem
#pragma unroll
    for (int mf = 0; mf < 4; mf++) {
#pragma unroll
        for (int h2 = 0; h2 < 2; h2++) {
            float s = acc_e[mf][h2];
            s += __shfl_xor_sync(0xffffffffu, s, 1, 4);
            s += __shfl_xor_sync(0xffffffffu, s, 2, 4);
            if (lc == 0)
                atomicAdd(&eSm[wm * 64 + mf * 16 + lr + h2 * 8], s);
        }
    }
    __syncthreads();
    if (tid < 128) g_e_t[row0 + tid] = eSm[tid];
}

// ---------------------------------------------------------------------------
__global__ __launch_bounds__(256) void softmax_kernel(
    const float* __restrict__ cov, float* __restrict__ a_out, float* __restrict__ ncov_out)
{
    int b = blockIdx.x;
    int tid = threadIdx.x;
    const float* e = g_e_t + b * TT;
    __shared__ float red[256];
    float ev[16];
    float m = -1e30f;
#pragma unroll
    for (int k = 0; k < 16; k++) { ev[k] = e[tid + k * 256]; m = fmaxf(m, ev[k]); }
    red[tid] = m; __syncthreads();
    for (int s = 128; s > 0; s >>= 1) {
        if (tid < s) red[tid] = fmaxf(red[tid], red[tid + s]);
        __syncthreads();
    }
    float M = red[0]; __syncthreads();
    float sum = 0.0f;
#pragma unroll
    for (int k = 0; k < 16; k++) { ev[k] = expf(ev[k] - M); sum += ev[k]; }
    red[tid] = sum; __syncthreads();
    for (int s = 128; s > 0; s >>= 1) {
        if (tid < s) red[tid] += red[tid + s];
        __syncthreads();
    }
    float inv = 1.0f / red[0];
#pragma unroll
    for (int k = 0; k < 16; k++) {
        int i = b * TT + tid + k * 256;
        float a = ev[k] * inv;
        a_out[i] = a;
        ncov_out[i] = cov[i] + a;
    }
}

__global__ __launch_bounds__(512) void context_kernel(
    const float* __restrict__ h, const float* __restrict__ a, float* __restrict__ ctx)
{
    int b = blockIdx.x >> 5;
    int tc = blockIdx.x & 31;
    int d = threadIdx.x;
    int t0 = tc * 128;
    const float* hp = h + ((size_t)b * TT + t0) * DD + d;
    const float* ap = a + b * TT + t0;
    float acc = 0.0f;
#pragma unroll 4
    for (int t = 0; t < 128; t++) acc += ap[t] * hp[(size_t)t * DD];
    atomicAdd(&ctx[b * DD + d], acc);
}

// ---------------------------------------------------------------------------
extern "C" void kernel_launch(void* const* d_in, const int* in_sizes, int n_in,
                              void* d_out, int out_size)
{
    const float* h   = (const float*)d_in[0];
    const float* s   = (const float*)d_in[1];
    const float* cov = (const float*)d_in[2];
    const float* Wh  = (const float*)d_in[3];
    const float* Ws  = (const float*)d_in[4];
    const float* bs  = (const float*)d_in[5];
    const float* Wc  = (const float*)d_in[6];
    const float* V   = (const float*)d_in[7];

    float* out   = (float*)d_out;
    float* ctx   = out;
    float* a_out = out + BATCH * DD;
    float* ncov  = a_out + MM;

    cudaFuncSetAttribute(fused_score_gemm,
                         cudaFuncAttributeMaxDynamicSharedMemorySize, SM_TOTAL);

    zero_kernel<<<64, 256>>>(ctx);
    prep_wh_kernel<<<1024, 256>>>(Wh);
    dec_kernel<<<64, 256>>>(s, Ws, bs);
    fused_score_gemm<<<MM / 128, 256, SM_TOTAL>>>(h, cov, Wc, V);
    softmax_kernel<<<BATCH, 256>>>(cov, a_out, ncov);
    context_kernel<<<BATCH * 32, 512>>>(h, a_out, ctx);
}